// round 6
// baseline (speedup 1.0000x reference)
#include <cuda_runtime.h>
#include <cuda_bf16.h>
#include <cstdint>
#include <math.h>

#define T_TOK  4096
#define HID    4096
#define IMOE   1024
#define ISH    4096
#define NEXP   16
#define NPAIR  8192
#define MAX_MT 80

// ---------------------------------------------------------------------------
// Static device scratch (allocation-free; sanctioned by harness rules)
// ---------------------------------------------------------------------------
static __device__ __nv_bfloat16 g_xs   [(size_t)T_TOK * 2 * HID];        //  64MB  x split [T][2H]
static __device__ __nv_bfloat16 g_wsgu [(size_t)2*ISH * 2 * HID];        // 128MB  shared gate_up split [8192][2H]
static __device__ __nv_bfloat16 g_wsd  [(size_t)HID * 2 * ISH];          //  64MB  shared down split [H][2*ISH]
static __device__ __nv_bfloat16 g_wgu  [(size_t)NEXP * 2*IMOE * 2*HID];  // 512MB  expert gate_up split
static __device__ __nv_bfloat16 g_wd   [(size_t)NEXP * HID * 2*IMOE];    // 256MB  expert down split
static __device__ float         g_gush [(size_t)T_TOK * 2 * ISH];        // 128MB  shared gu
static __device__ __nv_bfloat16 g_actsh[(size_t)T_TOK * 2 * ISH];        //  64MB  shared act split
static __device__ float         g_gup  [(size_t)NPAIR * 2 * IMOE];       //  64MB  moe gu (per pair)
static __device__ __nv_bfloat16 g_actp [(size_t)NPAIR * 2 * IMOE];       //  32MB  moe act split
static __device__ float         g_y    [(size_t)NPAIR * HID];            // 128MB  moe down out (per pair)

static __device__ int   g_counts[NEXP];
static __device__ int   g_offs[NEXP + 1];
static __device__ int   g_cursor[NEXP];
static __device__ int   g_eid[NPAIR];
static __device__ float g_wgt[NPAIR];
static __device__ int   g_perm[NPAIR];
static __device__ int   g_p2p[NPAIR];
static __device__ int   g_te[MAX_MT], g_tp0[MAX_MT], g_tcnt[MAX_MT];
static __device__ int   g_nmt[1];

// ---------------------------------------------------------------------------
// PTX helpers
// ---------------------------------------------------------------------------
__device__ __forceinline__ void cp16(uint32_t s, const void* g, int src_bytes) {
    asm volatile("cp.async.cg.shared.global [%0], [%1], 16, %2;\n"
                 :: "r"(s), "l"(g), "r"(src_bytes));
}
__device__ __forceinline__ void cp_commit() { asm volatile("cp.async.commit_group;\n"); }
__device__ __forceinline__ void cp_wait0()  { asm volatile("cp.async.wait_group 0;\n"); }

__device__ __forceinline__ void ldsm4(uint32_t* r, uint32_t a) {
    asm volatile("ldmatrix.sync.aligned.m8n8.x4.shared.b16 {%0,%1,%2,%3}, [%4];\n"
                 : "=r"(r[0]), "=r"(r[1]), "=r"(r[2]), "=r"(r[3]) : "r"(a));
}
__device__ __forceinline__ void ldsm2(uint32_t* r, uint32_t a) {
    asm volatile("ldmatrix.sync.aligned.m8n8.x2.shared.b16 {%0,%1}, [%2];\n"
                 : "=r"(r[0]), "=r"(r[1]) : "r"(a));
}
__device__ __forceinline__ void mma16816(float* c, const uint32_t* a, const uint32_t* b) {
    asm volatile("mma.sync.aligned.m16n8k16.row.col.f32.bf16.bf16.f32 "
                 "{%0,%1,%2,%3}, {%4,%5,%6,%7}, {%8,%9}, {%0,%1,%2,%3};\n"
                 : "+f"(c[0]), "+f"(c[1]), "+f"(c[2]), "+f"(c[3])
                 : "r"(a[0]), "r"(a[1]), "r"(a[2]), "r"(a[3]), "r"(b[0]), "r"(b[1]));
}

// XOR-swizzled smem offset: 128-byte rows (64 bf16), 8x 16B chunks per row.
__device__ __forceinline__ uint32_t swz(uint32_t row, uint32_t chunk) {
    return (row << 7) + (((chunk ^ (row & 7u)) & 7u) << 4);
}

// ---------------------------------------------------------------------------
// GEMM: C[M,N] += sum over 3 split-regions of A[m, 2K] x B[n, 2K]^T (bf16,
// fp32 accum). MODE 0: dense; MODE 1: grouped, A rows gathered via g_perm;
// MODE 2: grouped, A rows = output rows.
// Tiles 128x128x64, 256 threads, 2-stage cp.async pipeline, 64KB dyn smem.
// ---------------------------------------------------------------------------
template <int MODE>
__global__ void __launch_bounds__(256)
gemm_k(const __nv_bfloat16* __restrict__ A,
       const __nv_bfloat16* __restrict__ B,
       float* __restrict__ C,
       int M, int N, int K, size_t Bstride)
{
    const int tid  = threadIdx.x;
    const int warp = tid >> 5;
    const int lane = tid & 31;

    int mt_row0, cnt, nt, e = 0;
    if (MODE == 0) {
        const int tn = N >> 7;
        int bid = blockIdx.x;
        int per = 8 * tn;                  // tiles_m must be a multiple of 8
        int chunk = bid / per, rem = bid - chunk * per;
        int mtile = chunk * 8 + (rem & 7);
        nt = rem >> 3;
        mt_row0 = mtile << 7;
        cnt = 128;
    } else {
        if ((int)blockIdx.y >= g_nmt[0]) return;
        nt      = blockIdx.x;
        e       = g_te[blockIdx.y];
        mt_row0 = g_tp0[blockIdx.y];
        cnt     = g_tcnt[blockIdx.y];
    }
    const __nv_bfloat16* Bp = B + (size_t)e * Bstride;
    const int ld = 2 * K;

    extern __shared__ char smem[];
    const uint32_t smB = (uint32_t)__cvta_generic_to_shared(smem);
    // layout: A stage0 [0,16K) A stage1 [16K,32K) B stage0 [32K,48K) B stage1 [48K,64K)

    const int kit = K >> 6;       // iters per region
    const int NIT = 3 * kit;

    auto load_tiles = [&](int stage, int it) {
        int r  = it / kit;
        int kk = (it - r * kit) << 6;
        int acol = kk + (r == 1 ? K : 0);
        int bcol = kk + (r == 2 ? K : 0);
        uint32_t aB = smB + stage * 16384;
        uint32_t bB = smB + 32768 + stage * 16384;
#pragma unroll
        for (int i = 0; i < 4; i++) {
            int lin = i * 256 + tid;
            int row = lin >> 3, ch = lin & 7;
            // A tile
            size_t ga; int vb = 16;
            if (MODE == 0) {
                ga = (size_t)(mt_row0 + row) * ld + acol + ch * 8;
            } else if (MODE == 1) {
                int ok = (row < cnt);
                int rg = ok ? g_perm[mt_row0 + row] : 0;
                vb = ok ? 16 : 0;
                ga = (size_t)rg * ld + acol + ch * 8;
            } else {
                int ok = (row < cnt);
                int rg = ok ? (mt_row0 + row) : 0;
                vb = ok ? 16 : 0;
                ga = (size_t)rg * ld + acol + ch * 8;
            }
            cp16(aB + swz(row, ch), A + ga, vb);
            // B tile
            size_t gb = (size_t)(nt * 128 + row) * ld + bcol + ch * 8;
            cp16(bB + swz(row, ch), Bp + gb, 16);
        }
        cp_commit();
    };

    float acc[4][4][4];
#pragma unroll
    for (int a = 0; a < 4; a++)
#pragma unroll
        for (int b = 0; b < 4; b++)
#pragma unroll
            for (int c = 0; c < 4; c++) acc[a][b][c] = 0.f;

    const int wm = warp & 1;      // 0..1  (64-row slabs)
    const int wn = warp >> 1;     // 0..3  (32-col slabs)

    load_tiles(0, 0);

    for (int it = 0; it < NIT; ++it) {
        cp_wait0();
        __syncthreads();
        int cur = it & 1;
        if (it + 1 < NIT) load_tiles(cur ^ 1, it + 1);

        uint32_t aB = smB + cur * 16384;
        uint32_t bB = smB + 32768 + cur * 16384;
#pragma unroll
        for (int kk = 0; kk < 4; kk++) {
            uint32_t afr[4][4], bfr[4][2];
#pragma unroll
            for (int mi = 0; mi < 4; mi++) {
                int row = wm * 64 + mi * 16 + (lane & 15);
                int ch  = kk * 2 + ((lane >> 4) & 1);
                ldsm4(afr[mi], aB + swz(row, ch));
            }
#pragma unroll
            for (int ni = 0; ni < 4; ni++) {
                int row = wn * 32 + ni * 8 + (lane & 7);
                int ch  = kk * 2 + ((lane >> 3) & 1);
                ldsm2(bfr[ni], bB + swz(row, ch));
            }
#pragma unroll
            for (int mi = 0; mi < 4; mi++)
#pragma unroll
                for (int ni = 0; ni < 4; ni++)
                    mma16816(acc[mi][ni], afr[mi], bfr[ni]);
        }
    }

    // epilogue
#pragma unroll
    for (int mi = 0; mi < 4; mi++) {
        int lr0 = wm * 64 + mi * 16 + (lane >> 2);
        int lr1 = lr0 + 8;
#pragma unroll
        for (int ni = 0; ni < 4; ni++) {
            int c0 = nt * 128 + wn * 32 + ni * 8 + 2 * (lane & 3);
            if (MODE == 0 || lr0 < cnt) {
                float2 v = make_float2(acc[mi][ni][0], acc[mi][ni][1]);
                *(float2*)&C[(size_t)(mt_row0 + lr0) * N + c0] = v;
            }
            if (MODE == 0 || lr1 < cnt) {
                float2 v = make_float2(acc[mi][ni][2], acc[mi][ni][3]);
                *(float2*)&C[(size_t)(mt_row0 + lr1) * N + c0] = v;
            }
        }
    }
}

// ---------------------------------------------------------------------------
// Elementwise kernels
// ---------------------------------------------------------------------------
__global__ void split_kernel(const float* __restrict__ src,
                             __nv_bfloat16* __restrict__ dst,
                             int logC, size_t n)
{
    size_t i = (size_t)blockIdx.x * 256 + threadIdx.x;
    if (i >= n) return;
    size_t row = i >> logC;
    int    col = (int)(i & (((size_t)1 << logC) - 1));
    float v = src[i];
    __nv_bfloat16 h = __float2bfloat16(v);
    float lo = v - __bfloat162float(h);
    size_t base = (row << (logC + 1));
    dst[base + col] = h;
    dst[base + ((size_t)1 << logC) + col] = __float2bfloat16(lo);
}

__global__ void swiglu_split_kernel(const float* __restrict__ gu,
                                    __nv_bfloat16* __restrict__ act,
                                    int logI, size_t n)
{
    size_t i = (size_t)blockIdx.x * 256 + threadIdx.x;
    if (i >= n) return;
    size_t row = i >> logI;
    int    c   = (int)(i & (((size_t)1 << logI) - 1));
    size_t I   = (size_t)1 << logI;
    size_t base = row * 2 * I;
    float g = gu[base + c];
    float u = gu[base + I + c];
    float a = (g / (1.f + expf(-g))) * u;
    __nv_bfloat16 h = __float2bfloat16(a);
    float lo = a - __bfloat162float(h);
    act[base + c] = h;
    act[base + I + c] = __float2bfloat16(lo);
}

__global__ void init_kernel() {
    if (threadIdx.x < NEXP) g_counts[threadIdx.x] = 0;
}

__global__ void router_kernel(const float* __restrict__ x, const float* __restrict__ gw)
{
    __shared__ float slog[NEXP];
    int t = blockIdx.x;
    const float* xr = x + (size_t)t * HID;
    int tid = threadIdx.x;
    int e = tid >> 3, g = tid & 7;
    float s = 0.f;
    const float* w = gw + (size_t)e * HID;
    for (int k = g; k < HID; k += 8) s += xr[k] * w[k];
#pragma unroll
    for (int o = 4; o > 0; o >>= 1) s += __shfl_down_sync(0xffffffffu, s, o, 8);
    if (g == 0) slog[e] = s;
    __syncthreads();
    if (tid == 0) {
        int i0 = 0;
        float b0 = slog[0];
        for (int k = 1; k < NEXP; k++) if (slog[k] > b0) { b0 = slog[k]; i0 = k; }
        int i1 = -1;
        float b1 = -3.4e38f;
        for (int k = 0; k < NEXP; k++) {
            if (k == i0) continue;
            if (slog[k] > b1) { b1 = slog[k]; i1 = k; }
        }
        float m  = fmaxf(b0, b1);
        float e0 = expf(b0 - m), e1 = expf(b1 - m);
        float inv = 1.f / (e0 + e1);
        g_eid[2 * t] = i0;       g_eid[2 * t + 1] = i1;
        g_wgt[2 * t] = e0 * inv; g_wgt[2 * t + 1] = e1 * inv;
        atomicAdd(&g_counts[i0], 1);
        atomicAdd(&g_counts[i1], 1);
    }
}

__global__ void scan_kernel()
{
    if (threadIdx.x != 0 || blockIdx.x != 0) return;
    int off = 0;
    for (int e = 0; e < NEXP; e++) {
        g_offs[e] = off; g_cursor[e] = off; off += g_counts[e];
    }
    g_offs[NEXP] = off;
    int t = 0;
    for (int e = 0; e < NEXP; e++) {
        int c = g_counts[e];
        for (int j = 0; j * 128 < c; j++) {
            g_te[t]  = e;
            g_tp0[t] = g_offs[e] + j * 128;
            int rem  = c - j * 128;
            g_tcnt[t] = rem < 128 ? rem : 128;
            t++;
        }
    }
    g_nmt[0] = t;
}

__global__ void scatter_kernel()
{
    int p = blockIdx.x * 256 + threadIdx.x;
    if (p >= NPAIR) return;
    int e = g_eid[p];
    int pos = atomicAdd(&g_cursor[e], 1);
    g_perm[pos] = p >> 1;
    g_p2p[p] = pos;
}

__global__ void combine_kernel(float* __restrict__ out)
{
    size_t i = (size_t)blockIdx.x * 256 + threadIdx.x;
    if (i >= (size_t)T_TOK * HID) return;
    int t = (int)(i >> 12);
    int h = (int)(i & 4095);
    int p0 = g_p2p[2 * t], p1 = g_p2p[2 * t + 1];
    float v = g_wgt[2 * t]     * g_y[(size_t)p0 * HID + h]
            + g_wgt[2 * t + 1] * g_y[(size_t)p1 * HID + h];
    out[i] += v;
}

// ---------------------------------------------------------------------------
// Launch
// ---------------------------------------------------------------------------
extern "C" void kernel_launch(void* const* d_in, const int* in_sizes, int n_in,
                              void* d_out, int out_size)
{
    const float* x    = (const float*)d_in[0];
    const float* gw   = (const float*)d_in[1];
    const float* wgu  = (const float*)d_in[2];
    const float* wd   = (const float*)d_in[3];
    const float* swgu = (const float*)d_in[4];
    const float* swd  = (const float*)d_in[5];
    float* out = (float*)d_out;

    void *p_xs, *p_wsgu, *p_wsd, *p_wgu, *p_wd, *p_gush, *p_actsh, *p_gup, *p_actp, *p_y;
    cudaGetSymbolAddress(&p_xs,    g_xs);
    cudaGetSymbolAddress(&p_wsgu,  g_wsgu);
    cudaGetSymbolAddress(&p_wsd,   g_wsd);
    cudaGetSymbolAddress(&p_wgu,   g_wgu);
    cudaGetSymbolAddress(&p_wd,    g_wd);
    cudaGetSymbolAddress(&p_gush,  g_gush);
    cudaGetSymbolAddress(&p_actsh, g_actsh);
    cudaGetSymbolAddress(&p_gup,   g_gup);
    cudaGetSymbolAddress(&p_actp,  g_actp);
    cudaGetSymbolAddress(&p_y,     g_y);

    const int SMEM = 65536;
    cudaFuncSetAttribute(gemm_k<0>, cudaFuncAttributeMaxDynamicSharedMemorySize, SMEM);
    cudaFuncSetAttribute(gemm_k<1>, cudaFuncAttributeMaxDynamicSharedMemorySize, SMEM);
    cudaFuncSetAttribute(gemm_k<2>, cudaFuncAttributeMaxDynamicSharedMemorySize, SMEM);

    auto blk = [](size_t n) { return (unsigned)((n + 255) / 256); };

    // split inputs to bf16 hi/lo
    split_kernel<<<blk((size_t)T_TOK * HID),        256>>>(x,    (__nv_bfloat16*)p_xs,   12, (size_t)T_TOK * HID);
    split_kernel<<<blk((size_t)2 * ISH * HID),      256>>>(swgu, (__nv_bfloat16*)p_wsgu, 12, (size_t)2 * ISH * HID);
    split_kernel<<<blk((size_t)HID * ISH),          256>>>(swd,  (__nv_bfloat16*)p_wsd,  12, (size_t)HID * ISH);
    split_kernel<<<blk((size_t)NEXP * 2*IMOE * HID),256>>>(wgu,  (__nv_bfloat16*)p_wgu,  12, (size_t)NEXP * 2 * IMOE * HID);
    split_kernel<<<blk((size_t)NEXP * HID * IMOE),  256>>>(wd,   (__nv_bfloat16*)p_wd,   10, (size_t)NEXP * HID * IMOE);

    // router + grouping metadata
    init_kernel<<<1, 32>>>();
    router_kernel<<<T_TOK, 128>>>(x, gw);
    scan_kernel<<<1, 32>>>();
    scatter_kernel<<<blk(NPAIR), 256>>>();

    // shared MLP
    gemm_k<0><<<(T_TOK / 128) * (2 * ISH / 128), 256, SMEM>>>(
        (const __nv_bfloat16*)p_xs, (const __nv_bfloat16*)p_wsgu, (float*)p_gush,
        T_TOK, 2 * ISH, HID, 0);
    swiglu_split_kernel<<<blk((size_t)T_TOK * ISH), 256>>>(
        (const float*)p_gush, (__nv_bfloat16*)p_actsh, 12, (size_t)T_TOK * ISH);
    gemm_k<0><<<(T_TOK / 128) * (HID / 128), 256, SMEM>>>(
        (const __nv_bfloat16*)p_actsh, (const __nv_bfloat16*)p_wsd, out,
        T_TOK, HID, ISH, 0);

    // grouped MoE
    gemm_k<1><<<dim3(2 * IMOE / 128, MAX_MT), 256, SMEM>>>(
        (const __nv_bfloat16*)p_xs, (const __nv_bfloat16*)p_wgu, (float*)p_gup,
        0, 2 * IMOE, HID, (size_t)(2 * IMOE) * (2 * HID));
    swiglu_split_kernel<<<blk((size_t)NPAIR * IMOE), 256>>>(
        (const float*)p_gup, (__nv_bfloat16*)p_actp, 10, (size_t)NPAIR * IMOE);
    gemm_k<2><<<dim3(HID / 128, MAX_MT), 256, SMEM>>>(
        (const __nv_bfloat16*)p_actp, (const __nv_bfloat16*)p_wd, (float*)p_y,
        0, HID, IMOE, (size_t)HID * (2 * IMOE));

    // combine: out += w0*y[p0] + w1*y[p1]
    combine_kernel<<<blk((size_t)T_TOK * HID), 256>>>(out);
}

// round 7
// speedup vs baseline: 3.0594x; 3.0594x over previous
#include <cuda_runtime.h>
#include <cuda_bf16.h>
#include <cuda_fp16.h>
#include <cstdint>
#include <math.h>

#define T_TOK  4096
#define HID    4096
#define IMOE   1024
#define ISH    4096
#define NEXP   16
#define NPAIR  8192
#define MAX_MT 80

// ---------------------------------------------------------------------------
// Static device scratch (allocation-free; sanctioned by harness rules)
// ---------------------------------------------------------------------------
static __device__ __half g_xs   [(size_t)T_TOK * HID];           //  32MB  x fp16
static __device__ __half g_wsgu [(size_t)2*ISH * HID];           //  64MB  shared gate_up fp16
static __device__ __half g_wsd  [(size_t)HID * ISH];             //  32MB  shared down fp16
static __device__ __half g_wgu  [(size_t)NEXP * 2*IMOE * HID];   // 256MB  expert gate_up fp16
static __device__ __half g_wd   [(size_t)NEXP * HID * IMOE];     // 128MB  expert down fp16
static __device__ float  g_gush [(size_t)T_TOK * 2 * ISH];       // 128MB  shared gu fp32
static __device__ __half g_actsh[(size_t)T_TOK * ISH];           //  32MB  shared act fp16
static __device__ float  g_gup  [(size_t)NPAIR * 2 * IMOE];      //  64MB  moe gu fp32
static __device__ __half g_actp [(size_t)NPAIR * IMOE];          //  16MB  moe act fp16
static __device__ float  g_y    [(size_t)NPAIR * HID];           // 128MB  moe down out

static __device__ int   g_counts[NEXP];
static __device__ int   g_offs[NEXP + 1];
static __device__ int   g_cursor[NEXP];
static __device__ int   g_eid[NPAIR];
static __device__ float g_wgt[NPAIR];
static __device__ int   g_perm[NPAIR];
static __device__ int   g_p2p[NPAIR];
static __device__ int   g_te[MAX_MT], g_tp0[MAX_MT], g_tcnt[MAX_MT];
static __device__ int   g_nmt[1];

// ---------------------------------------------------------------------------
// PTX helpers
// ---------------------------------------------------------------------------
__device__ __forceinline__ void cp16(uint32_t s, const void* g, int src_bytes) {
    asm volatile("cp.async.cg.shared.global [%0], [%1], 16, %2;\n"
                 :: "r"(s), "l"(g), "r"(src_bytes));
}
__device__ __forceinline__ void cp_commit() { asm volatile("cp.async.commit_group;\n"); }
__device__ __forceinline__ void cp_wait0()  { asm volatile("cp.async.wait_group 0;\n"); }
__device__ __forceinline__ void cp_wait1()  { asm volatile("cp.async.wait_group 1;\n"); }

__device__ __forceinline__ void ldsm4(uint32_t* r, uint32_t a) {
    asm volatile("ldmatrix.sync.aligned.m8n8.x4.shared.b16 {%0,%1,%2,%3}, [%4];\n"
                 : "=r"(r[0]), "=r"(r[1]), "=r"(r[2]), "=r"(r[3]) : "r"(a));
}
__device__ __forceinline__ void ldsm2(uint32_t* r, uint32_t a) {
    asm volatile("ldmatrix.sync.aligned.m8n8.x2.shared.b16 {%0,%1}, [%2];\n"
                 : "=r"(r[0]), "=r"(r[1]) : "r"(a));
}
__device__ __forceinline__ void mma16816(float* c, const uint32_t* a, const uint32_t* b) {
    asm volatile("mma.sync.aligned.m16n8k16.row.col.f32.f16.f16.f32 "
                 "{%0,%1,%2,%3}, {%4,%5,%6,%7}, {%8,%9}, {%0,%1,%2,%3};\n"
                 : "+f"(c[0]), "+f"(c[1]), "+f"(c[2]), "+f"(c[3])
                 : "r"(a[0]), "r"(a[1]), "r"(a[2]), "r"(a[3]), "r"(b[0]), "r"(b[1]));
}

// XOR-swizzled smem offset: 128-byte rows (64 f16), 8x 16B chunks per row.
__device__ __forceinline__ uint32_t swz(uint32_t row, uint32_t chunk) {
    return (row << 7) + (((chunk ^ (row & 7u)) & 7u) << 4);
}

// ---------------------------------------------------------------------------
// GEMM: C[M,N] = A[M,K] x B[N,K]^T  (fp16 in, fp32 accum/out).
// MODE 0: dense; MODE 1: grouped, A rows gathered via g_perm;
// MODE 2: grouped, A rows = output rows.
// Tiles 128x128x64, 256 threads, 3-stage cp.async pipeline, 96KB dyn smem.
// ---------------------------------------------------------------------------
template <int MODE>
__global__ void __launch_bounds__(256)
gemm_k(const __half* __restrict__ A,
       const __half* __restrict__ B,
       float* __restrict__ C,
       int M, int N, int K, size_t Bstride)
{
    const int tid  = threadIdx.x;
    const int warp = tid >> 5;
    const int lane = tid & 31;

    int mt_row0, cnt, nt, e = 0;
    if (MODE == 0) {
        const int tn = N >> 7;
        int bid = blockIdx.x;
        int per = 8 * tn;                  // tiles_m must be a multiple of 8
        int chunk = bid / per, rem = bid - chunk * per;
        int mtile = chunk * 8 + (rem & 7);
        nt = rem >> 3;
        mt_row0 = mtile << 7;
        cnt = 128;
    } else {
        if ((int)blockIdx.y >= g_nmt[0]) return;
        nt      = blockIdx.x;
        e       = g_te[blockIdx.y];
        mt_row0 = g_tp0[blockIdx.y];
        cnt     = g_tcnt[blockIdx.y];
    }
    const __half* Bp = B + (size_t)e * Bstride;

    extern __shared__ char smem[];
    const uint32_t smB = (uint32_t)__cvta_generic_to_shared(smem);
    // layout: A stages [0,48K) 3x16K, B stages [48K,96K) 3x16K

    const int NIT = K >> 6;   // >= 16 always

    auto load_tiles = [&](int stage, int it) {
        int kk = it << 6;
        uint32_t aB = smB + stage * 16384;
        uint32_t bB = smB + 49152 + stage * 16384;
#pragma unroll
        for (int i = 0; i < 4; i++) {
            int lin = i * 256 + tid;
            int row = lin >> 3, ch = lin & 7;
            // A tile
            size_t ga; int vb = 16;
            if (MODE == 0) {
                ga = (size_t)(mt_row0 + row) * K + kk + ch * 8;
            } else if (MODE == 1) {
                int ok = (row < cnt);
                int rg = ok ? g_perm[mt_row0 + row] : 0;
                vb = ok ? 16 : 0;
                ga = (size_t)rg * K + kk + ch * 8;
            } else {
                int ok = (row < cnt);
                int rg = ok ? (mt_row0 + row) : 0;
                vb = ok ? 16 : 0;
                ga = (size_t)rg * K + kk + ch * 8;
            }
            cp16(aB + swz(row, ch), A + ga, vb);
            // B tile
            size_t gb = (size_t)(nt * 128 + row) * K + kk + ch * 8;
            cp16(bB + swz(row, ch), Bp + gb, 16);
        }
        cp_commit();
    };

    float acc[4][4][4];
#pragma unroll
    for (int a = 0; a < 4; a++)
#pragma unroll
        for (int b = 0; b < 4; b++)
#pragma unroll
            for (int c = 0; c < 4; c++) acc[a][b][c] = 0.f;

    const int wm = warp & 1;      // 0..1  (64-row slabs)
    const int wn = warp >> 1;     // 0..3  (32-col slabs)

    load_tiles(0, 0);
    load_tiles(1, 1);

    for (int it = 0; it < NIT; ++it) {
        if (it == NIT - 1) cp_wait0(); else cp_wait1();
        __syncthreads();
        int cur = it % 3;
        if (it + 2 < NIT) load_tiles((it + 2) % 3, it + 2);

        uint32_t aB = smB + cur * 16384;
        uint32_t bB = smB + 49152 + cur * 16384;
#pragma unroll
        for (int kk = 0; kk < 4; kk++) {
            uint32_t afr[4][4], bfr[4][2];
#pragma unroll
            for (int mi = 0; mi < 4; mi++) {
                int row = wm * 64 + mi * 16 + (lane & 15);
                int ch  = kk * 2 + ((lane >> 4) & 1);
                ldsm4(afr[mi], aB + swz(row, ch));
            }
#pragma unroll
            for (int ni = 0; ni < 4; ni++) {
                int row = wn * 32 + ni * 8 + (lane & 7);
                int ch  = kk * 2 + ((lane >> 3) & 1);
                ldsm2(bfr[ni], bB + swz(row, ch));
            }
#pragma unroll
            for (int mi = 0; mi < 4; mi++)
#pragma unroll
                for (int ni = 0; ni < 4; ni++)
                    mma16816(acc[mi][ni], afr[mi], bfr[ni]);
        }
        __syncthreads();
    }

    // epilogue
#pragma unroll
    for (int mi = 0; mi < 4; mi++) {
        int lr0 = wm * 64 + mi * 16 + (lane >> 2);
        int lr1 = lr0 + 8;
#pragma unroll
        for (int ni = 0; ni < 4; ni++) {
            int c0 = nt * 128 + wn * 32 + ni * 8 + 2 * (lane & 3);
            if (MODE == 0 || lr0 < cnt) {
                float2 v = make_float2(acc[mi][ni][0], acc[mi][ni][1]);
                *(float2*)&C[(size_t)(mt_row0 + lr0) * N + c0] = v;
            }
            if (MODE == 0 || lr1 < cnt) {
                float2 v = make_float2(acc[mi][ni][2], acc[mi][ni][3]);
                *(float2*)&C[(size_t)(mt_row0 + lr1) * N + c0] = v;
            }
        }
    }
}

// ---------------------------------------------------------------------------
// Elementwise kernels (vectorized x4)
// ---------------------------------------------------------------------------
__global__ void cvt_kernel(const float4* __restrict__ src,
                           uint2* __restrict__ dst, size_t n4)
{
    size_t i = (size_t)blockIdx.x * 256 + threadIdx.x;
    if (i >= n4) return;
    float4 v = src[i];
    __half2 lo = __floats2half2_rn(v.x, v.y);
    __half2 hi = __floats2half2_rn(v.z, v.w);
    uint2 o;
    o.x = *(uint32_t*)&lo;
    o.y = *(uint32_t*)&hi;
    dst[i] = o;
}

__global__ void swiglu_kernel(const float* __restrict__ gu,
                              __half* __restrict__ act,
                              int logI, size_t n4)
{
    size_t i4 = (size_t)blockIdx.x * 256 + threadIdx.x;
    if (i4 >= n4) return;
    size_t i   = i4 << 2;
    size_t I   = (size_t)1 << logI;
    size_t row = i >> logI;
    int    c   = (int)(i & (I - 1));
    size_t base = row * 2 * I;
    float4 g = *(const float4*)&gu[base + c];
    float4 u = *(const float4*)&gu[base + I + c];
    float a0 = (g.x / (1.f + expf(-g.x))) * u.x;
    float a1 = (g.y / (1.f + expf(-g.y))) * u.y;
    float a2 = (g.z / (1.f + expf(-g.z))) * u.z;
    float a3 = (g.w / (1.f + expf(-g.w))) * u.w;
    __half2 lo = __floats2half2_rn(a0, a1);
    __half2 hi = __floats2half2_rn(a2, a3);
    uint2 o;
    o.x = *(uint32_t*)&lo;
    o.y = *(uint32_t*)&hi;
    *(uint2*)&act[row * I + c] = o;
}

__global__ void init_kernel() {
    if (threadIdx.x < NEXP) g_counts[threadIdx.x] = 0;
}

__global__ void router_kernel(const float* __restrict__ x, const float* __restrict__ gw)
{
    __shared__ float slog[NEXP];
    int t = blockIdx.x;
    const float* xr = x + (size_t)t * HID;
    int tid = threadIdx.x;
    int e = tid >> 3, g = tid & 7;
    float s = 0.f;
    const float* w = gw + (size_t)e * HID;
    for (int k = g; k < HID; k += 8) s += xr[k] * w[k];
#pragma unroll
    for (int o = 4; o > 0; o >>= 1) s += __shfl_down_sync(0xffffffffu, s, o, 8);
    if (g == 0) slog[e] = s;
    __syncthreads();
    if (tid == 0) {
        int i0 = 0;
        float b0 = slog[0];
        for (int k = 1; k < NEXP; k++) if (slog[k] > b0) { b0 = slog[k]; i0 = k; }
        int i1 = -1;
        float b1 = -3.4e38f;
        for (int k = 0; k < NEXP; k++) {
            if (k == i0) continue;
            if (slog[k] > b1) { b1 = slog[k]; i1 = k; }
        }
        float m  = fmaxf(b0, b1);
        float e0 = expf(b0 - m), e1 = expf(b1 - m);
        float inv = 1.f / (e0 + e1);
        g_eid[2 * t] = i0;       g_eid[2 * t + 1] = i1;
        g_wgt[2 * t] = e0 * inv; g_wgt[2 * t + 1] = e1 * inv;
        atomicAdd(&g_counts[i0], 1);
        atomicAdd(&g_counts[i1], 1);
    }
}

__global__ void scan_kernel()
{
    if (threadIdx.x != 0 || blockIdx.x != 0) return;
    int off = 0;
    for (int e = 0; e < NEXP; e++) {
        g_offs[e] = off; g_cursor[e] = off; off += g_counts[e];
    }
    g_offs[NEXP] = off;
    int t = 0;
    for (int e = 0; e < NEXP; e++) {
        int c = g_counts[e];
        for (int j = 0; j * 128 < c; j++) {
            g_te[t]  = e;
            g_tp0[t] = g_offs[e] + j * 128;
            int rem  = c - j * 128;
            g_tcnt[t] = rem < 128 ? rem : 128;
            t++;
        }
    }
    g_nmt[0] = t;
}

__global__ void scatter_kernel()
{
    int p = blockIdx.x * 256 + threadIdx.x;
    if (p >= NPAIR) return;
    int e = g_eid[p];
    int pos = atomicAdd(&g_cursor[e], 1);
    g_perm[pos] = p >> 1;
    g_p2p[p] = pos;
}

__global__ void combine_kernel(float* __restrict__ out)
{
    size_t i4 = (size_t)blockIdx.x * 256 + threadIdx.x;
    if (i4 >= (size_t)T_TOK * HID / 4) return;
    size_t i = i4 << 2;
    int t = (int)(i >> 12);
    int h = (int)(i & 4095);
    int p0 = g_p2p[2 * t], p1 = g_p2p[2 * t + 1];
    float w0 = g_wgt[2 * t], w1 = g_wgt[2 * t + 1];
    float4 y0 = *(const float4*)&g_y[(size_t)p0 * HID + h];
    float4 y1 = *(const float4*)&g_y[(size_t)p1 * HID + h];
    float4 o  = *(float4*)&out[i];
    o.x += w0 * y0.x + w1 * y1.x;
    o.y += w0 * y0.y + w1 * y1.y;
    o.z += w0 * y0.z + w1 * y1.z;
    o.w += w0 * y0.w + w1 * y1.w;
    *(float4*)&out[i] = o;
}

// ---------------------------------------------------------------------------
// Launch
// ---------------------------------------------------------------------------
extern "C" void kernel_launch(void* const* d_in, const int* in_sizes, int n_in,
                              void* d_out, int out_size)
{
    const float* x    = (const float*)d_in[0];
    const float* gw   = (const float*)d_in[1];
    const float* wgu  = (const float*)d_in[2];
    const float* wd   = (const float*)d_in[3];
    const float* swgu = (const float*)d_in[4];
    const float* swd  = (const float*)d_in[5];
    float* out = (float*)d_out;

    void *p_xs, *p_wsgu, *p_wsd, *p_wgu, *p_wd, *p_gush, *p_actsh, *p_gup, *p_actp;
    cudaGetSymbolAddress(&p_xs,    g_xs);
    cudaGetSymbolAddress(&p_wsgu,  g_wsgu);
    cudaGetSymbolAddress(&p_wsd,   g_wsd);
    cudaGetSymbolAddress(&p_wgu,   g_wgu);
    cudaGetSymbolAddress(&p_wd,    g_wd);
    cudaGetSymbolAddress(&p_gush,  g_gush);
    cudaGetSymbolAddress(&p_actsh, g_actsh);
    cudaGetSymbolAddress(&p_gup,   g_gup);
    cudaGetSymbolAddress(&p_actp,  g_actp);
    void* p_y;
    cudaGetSymbolAddress(&p_y,     g_y);

    const int SMEM = 98304;
    cudaFuncSetAttribute(gemm_k<0>, cudaFuncAttributeMaxDynamicSharedMemorySize, SMEM);
    cudaFuncSetAttribute(gemm_k<1>, cudaFuncAttributeMaxDynamicSharedMemorySize, SMEM);
    cudaFuncSetAttribute(gemm_k<2>, cudaFuncAttributeMaxDynamicSharedMemorySize, SMEM);

    auto blk4 = [](size_t n) { return (unsigned)((n / 4 + 255) / 256); };

    // fp32 -> fp16 converts
    cvt_kernel<<<blk4((size_t)T_TOK * HID),           256>>>((const float4*)x,    (uint2*)p_xs,   (size_t)T_TOK * HID / 4);
    cvt_kernel<<<blk4((size_t)2 * ISH * HID),         256>>>((const float4*)swgu, (uint2*)p_wsgu, (size_t)2 * ISH * HID / 4);
    cvt_kernel<<<blk4((size_t)HID * ISH),             256>>>((const float4*)swd,  (uint2*)p_wsd,  (size_t)HID * ISH / 4);
    cvt_kernel<<<blk4((size_t)NEXP * 2 * IMOE * HID), 256>>>((const float4*)wgu,  (uint2*)p_wgu,  (size_t)NEXP * 2 * IMOE * HID / 4);
    cvt_kernel<<<blk4((size_t)NEXP * HID * IMOE),     256>>>((const float4*)wd,   (uint2*)p_wd,   (size_t)NEXP * HID * IMOE / 4);

    // router + grouping metadata
    init_kernel<<<1, 32>>>();
    router_kernel<<<T_TOK, 128>>>(x, gw);
    scan_kernel<<<1, 32>>>();
    scatter_kernel<<<(NPAIR + 255) / 256, 256>>>();

    // shared MLP
    gemm_k<0><<<(T_TOK / 128) * (2 * ISH / 128), 256, SMEM>>>(
        (const __half*)p_xs, (const __half*)p_wsgu, (float*)p_gush,
        T_TOK, 2 * ISH, HID, 0);
    swiglu_kernel<<<blk4((size_t)T_TOK * ISH), 256>>>(
        (const float*)p_gush, (__half*)p_actsh, 12, (size_t)T_TOK * ISH / 4);
    gemm_k<0><<<(T_TOK / 128) * (HID / 128), 256, SMEM>>>(
        (const __half*)p_actsh, (const __half*)p_wsd, out,
        T_TOK, HID, ISH, 0);

    // grouped MoE
    gemm_k<1><<<dim3(2 * IMOE / 128, MAX_MT), 256, SMEM>>>(
        (const __half*)p_xs, (const __half*)p_wgu, (float*)p_gup,
        0, 2 * IMOE, HID, (size_t)(2 * IMOE) * HID);
    swiglu_kernel<<<blk4((size_t)NPAIR * IMOE), 256>>>(
        (const float*)p_gup, (__half*)p_actp, 10, (size_t)NPAIR * IMOE / 4);
    gemm_k<2><<<dim3(HID / 128, MAX_MT), 256, SMEM>>>(
        (const __half*)p_actp, (const __half*)p_wd, (float*)p_y,
        0, HID, IMOE, (size_t)HID * IMOE);

    // combine: out += w0*y[p0] + w1*y[p1]
    combine_kernel<<<blk4((size_t)T_TOK * HID), 256>>>(out);
}

// round 11
// speedup vs baseline: 3.2027x; 1.0468x over previous
#include <cuda_runtime.h>
#include <cuda_bf16.h>
#include <cuda_fp16.h>
#include <cstdint>
#include <math.h>

#define T_TOK  4096
#define HID    4096
#define IMOE   1024
#define ISH    4096
#define NEXP   16
#define NPAIR  8192
#define MAX_MT 80
#define NSTG   3

// ---------------------------------------------------------------------------
// Static device scratch
// ---------------------------------------------------------------------------
static __device__ __half g_xs   [(size_t)T_TOK * HID];
static __device__ __half g_wsgu [(size_t)2*ISH * HID];
static __device__ __half g_wsd  [(size_t)HID * ISH];
static __device__ __half g_wgu  [(size_t)NEXP * 2*IMOE * HID];
static __device__ __half g_wd   [(size_t)NEXP * HID * IMOE];
static __device__ __half g_actsh[(size_t)T_TOK * ISH];
static __device__ __half g_actp [(size_t)NPAIR * IMOE];
static __device__ float  g_y    [(size_t)NPAIR * HID];

static __device__ int   g_counts[NEXP];
static __device__ int   g_offs[NEXP + 1];
static __device__ int   g_cursor[NEXP];
static __device__ int   g_eid[NPAIR];
static __device__ float g_wgt[NPAIR];
static __device__ int   g_perm[NPAIR];
static __device__ int   g_p2p[NPAIR];
static __device__ int   g_te[MAX_MT], g_tp0[MAX_MT], g_tcnt[MAX_MT];
static __device__ int   g_nmt[1];

// ---------------------------------------------------------------------------
// PTX helpers (Ampere-class only; proven on this harness in R6/R7)
// ---------------------------------------------------------------------------
__device__ __forceinline__ void cp16(uint32_t s, const void* g, int src_bytes) {
    asm volatile("cp.async.cg.shared.global [%0], [%1], 16, %2;\n"
                 :: "r"(s), "l"(g), "r"(src_bytes));
}
__device__ __forceinline__ void cp_commit() { asm volatile("cp.async.commit_group;\n"); }
__device__ __forceinline__ void cp_wait0()  { asm volatile("cp.async.wait_group 0;\n"); }
__device__ __forceinline__ void cp_wait1()  { asm volatile("cp.async.wait_group 1;\n"); }

__device__ __forceinline__ void ldsm4(uint32_t* r, uint32_t a) {
    asm volatile("ldmatrix.sync.aligned.m8n8.x4.shared.b16 {%0,%1,%2,%3}, [%4];\n"
                 : "=r"(r[0]), "=r"(r[1]), "=r"(r[2]), "=r"(r[3]) : "r"(a));
}
__device__ __forceinline__ void ldsm2(uint32_t* r, uint32_t a) {
    asm volatile("ldmatrix.sync.aligned.m8n8.x2.shared.b16 {%0,%1}, [%2];\n"
                 : "=r"(r[0]), "=r"(r[1]) : "r"(a));
}
__device__ __forceinline__ void mma16816(float* c, const uint32_t* a, const uint32_t* b) {
    asm volatile("mma.sync.aligned.m16n8k16.row.col.f32.f16.f16.f32 "
                 "{%0,%1,%2,%3}, {%4,%5,%6,%7}, {%8,%9}, {%0,%1,%2,%3};\n"
                 : "+f"(c[0]), "+f"(c[1]), "+f"(c[2]), "+f"(c[3])
                 : "r"(a[0]), "r"(a[1]), "r"(a[2]), "r"(a[3]), "r"(b[0]), "r"(b[1]));
}

// XOR-swizzled smem offset: 128-byte rows (64 f16), 8x 16B chunks per row.
__device__ __forceinline__ uint32_t swz(uint32_t row, uint32_t chunk) {
    return (row << 7) + (((chunk ^ (row & 7u)) & 7u) << 4);
}

__device__ __forceinline__ float silu_mul(float g, float u) {
    return (g / (1.f + expf(-g))) * u;
}

// ---------------------------------------------------------------------------
// GEMM (R7-proven envelope): tile 128x128x64, 256 threads, 3-stage cp.async,
// 96KB smem, fp16 in / fp32 accum.
// MODE 0 dense; MODE 1 grouped, A rows via g_perm; MODE 2 grouped identity.
// SWIGLU 0: C fp32 [*, Nact], tile cols nt*128..+127 (B has Nact rows).
// SWIGLU 1: B has 2*Nact rows (gu). B-tile rows remapped into 32-row slabs of
//           [16 g | 16 u] covering act cols nt*64..+63; epilogue applies
//           silu(g)*u and writes fp16 act [*, Nact].
// ---------------------------------------------------------------------------
template <int MODE, int SWIGLU>
__global__ void __launch_bounds__(256)
gemm_k(const __half* __restrict__ A, const __half* __restrict__ B,
       void* __restrict__ Cout, int Nact, int K, size_t Bstride, int ntiles)
{
    const int tid  = threadIdx.x;
    const int warp = tid >> 5;
    const int lane = tid & 31;

    int mt_row0, cnt, nt, e = 0;
    if (MODE == 0) {
        int per = 8 * ntiles;                 // m-tile count must be mult of 8
        int chunk = blockIdx.x / per, rem = blockIdx.x - chunk * per;
        mt_row0 = (chunk * 8 + (rem & 7)) << 7;
        nt = rem >> 3;
        cnt = 128;
    } else {
        if ((int)blockIdx.y >= g_nmt[0]) return;
        nt      = blockIdx.x;
        e       = g_te[blockIdx.y];
        mt_row0 = g_tp0[blockIdx.y];
        cnt     = g_tcnt[blockIdx.y];
    }
    const __half* Bp = B + (size_t)e * Bstride;

    extern __shared__ char smem[];   // 3 stages x (A 16KB + B 16KB)
    const uint32_t smB = (uint32_t)__cvta_generic_to_shared(smem);

    const int NIT = K >> 6;

    auto load_tiles = [&](int stage, int it) {
        int kk = it << 6;
        uint32_t aB = smB + stage * 32768;
        uint32_t bB = aB + 16384;
#pragma unroll
        for (int i = 0; i < 4; i++) {
            int lin = i * 256 + tid;
            int row = lin >> 3, ch = lin & 7;
            // A tile row
            size_t ga; int vb = 16;
            if (MODE == 0) {
                ga = (size_t)(mt_row0 + row) * K + kk + ch * 8;
            } else if (MODE == 1) {
                int ok = (row < cnt);
                int rg = ok ? g_perm[mt_row0 + row] : 0;
                vb = ok ? 16 : 0;
                ga = (size_t)rg * K + kk + ch * 8;
            } else {
                int ok = (row < cnt);
                int rg = ok ? (mt_row0 + row) : 0;
                vb = ok ? 16 : 0;
                ga = (size_t)rg * K + kk + ch * 8;
            }
            cp16(aB + swz(row, ch), A + ga, vb);
            // B tile row
            int brow;
            if (SWIGLU) {
                int s = row >> 5, w = row & 31;       // slab s: [16 g | 16 u]
                brow = (w < 16) ? (nt * 64 + s * 16 + w)
                                : (Nact + nt * 64 + s * 16 + (w - 16));
            } else {
                brow = nt * 128 + row;
            }
            cp16(bB + swz(row, ch), Bp + (size_t)brow * K + kk + ch * 8, 16);
        }
        cp_commit();
    };

    float acc[4][4][4];
#pragma unroll
    for (int a = 0; a < 4; a++)
#pragma unroll
        for (int b = 0; b < 4; b++)
#pragma unroll
            for (int c = 0; c < 4; c++) acc[a][b][c] = 0.f;

    const int wm = warp & 1;      // 0..1  (64-row slabs)
    const int wn = warp >> 1;     // 0..3  (32-B-row slabs)

    load_tiles(0, 0);
    load_tiles(1, 1);

    for (int it = 0; it < NIT; ++it) {
        if (it == NIT - 1) cp_wait0(); else cp_wait1();
        __syncthreads();
        int cur = it % NSTG;
        if (it + 2 < NIT) load_tiles((it + 2) % NSTG, it + 2);

        uint32_t aB = smB + cur * 32768;
        uint32_t bB = aB + 16384;
#pragma unroll
        for (int kk = 0; kk < 4; kk++) {
            uint32_t afr[4][4], bfr[4][2];
#pragma unroll
            for (int mi = 0; mi < 4; mi++) {
                int row = wm * 64 + mi * 16 + (lane & 15);
                int ch  = kk * 2 + ((lane >> 4) & 1);
                ldsm4(afr[mi], aB + swz(row, ch));
            }
#pragma unroll
            for (int ni = 0; ni < 4; ni++) {
                int row = wn * 32 + ni * 8 + (lane & 7);
                int ch  = kk * 2 + ((lane >> 3) & 1);
                ldsm2(bfr[ni], bB + swz(row, ch));
            }
#pragma unroll
            for (int mi = 0; mi < 4; mi++)
#pragma unroll
                for (int ni = 0; ni < 4; ni++)
                    mma16816(acc[mi][ni], afr[mi], bfr[ni]);
        }
        __syncthreads();
    }

    // ---------------- epilogue ----------------
#pragma unroll
    for (int mi = 0; mi < 4; mi++) {
        int lr0 = wm * 64 + mi * 16 + (lane >> 2);
        int lr1 = lr0 + 8;
        int v0 = (MODE == 0) || (lr0 < cnt);
        int v1 = (MODE == 0) || (lr1 < cnt);
        if (SWIGLU) {
            __half* act = (__half*)Cout;
#pragma unroll
            for (int ni = 0; ni < 2; ni++) {
                // acc[mi][ni] = g for cols, acc[mi][ni+2] = u for same cols
                size_t col = nt * 64 + wn * 16 + ni * 8 + 2 * (lane & 3);
                if (v0) {
                    __half2 h = __floats2half2_rn(
                        silu_mul(acc[mi][ni][0], acc[mi][ni + 2][0]),
                        silu_mul(acc[mi][ni][1], acc[mi][ni + 2][1]));
                    *(__half2*)&act[(size_t)(mt_row0 + lr0) * Nact + col] = h;
                }
                if (v1) {
                    __half2 h = __floats2half2_rn(
                        silu_mul(acc[mi][ni][2], acc[mi][ni + 2][2]),
                        silu_mul(acc[mi][ni][3], acc[mi][ni + 2][3]));
                    *(__half2*)&act[(size_t)(mt_row0 + lr1) * Nact + col] = h;
                }
            }
        } else {
            float* C = (float*)Cout;
#pragma unroll
            for (int ni = 0; ni < 4; ni++) {
                size_t col = nt * 128 + wn * 32 + ni * 8 + 2 * (lane & 3);
                if (v0) {
                    float2 v = make_float2(acc[mi][ni][0], acc[mi][ni][1]);
                    *(float2*)&C[(size_t)(mt_row0 + lr0) * Nact + col] = v;
                }
                if (v1) {
                    float2 v = make_float2(acc[mi][ni][2], acc[mi][ni][3]);
                    *(float2*)&C[(size_t)(mt_row0 + lr1) * Nact + col] = v;
                }
            }
        }
    }
}

// ---------------------------------------------------------------------------
// Elementwise / router kernels (unchanged from passing R7)
// ---------------------------------------------------------------------------
__global__ void cvt_kernel(const float4* __restrict__ src,
                           uint2* __restrict__ dst, size_t n4)
{
    size_t i = (size_t)blockIdx.x * 256 + threadIdx.x;
    if (i >= n4) return;
    float4 v = src[i];
    __half2 lo = __floats2half2_rn(v.x, v.y);
    __half2 hi = __floats2half2_rn(v.z, v.w);
    uint2 o;
    o.x = *(uint32_t*)&lo;
    o.y = *(uint32_t*)&hi;
    dst[i] = o;
}

__global__ void init_kernel() {
    if (threadIdx.x < NEXP) g_counts[threadIdx.x] = 0;
}

__global__ void router_kernel(const float* __restrict__ x, const float* __restrict__ gw)
{
    __shared__ float slog[NEXP];
    int t = blockIdx.x;
    const float* xr = x + (size_t)t * HID;
    int tid = threadIdx.x;
    int e = tid >> 3, g = tid & 7;
    float s = 0.f;
    const float* w = gw + (size_t)e * HID;
    for (int k = g; k < HID; k += 8) s += xr[k] * w[k];
#pragma unroll
    for (int o = 4; o > 0; o >>= 1) s += __shfl_down_sync(0xffffffffu, s, o, 8);
    if (g == 0) slog[e] = s;
    __syncthreads();
    if (tid == 0) {
        int i0 = 0;
        float b0 = slog[0];
        for (int k = 1; k < NEXP; k++) if (slog[k] > b0) { b0 = slog[k]; i0 = k; }
        int i1 = -1;
        float b1 = -3.4e38f;
        for (int k = 0; k < NEXP; k++) {
            if (k == i0) continue;
            if (slog[k] > b1) { b1 = slog[k]; i1 = k; }
        }
        float m  = fmaxf(b0, b1);
        float e0 = expf(b0 - m), e1 = expf(b1 - m);
        float inv = 1.f / (e0 + e1);
        g_eid[2 * t] = i0;       g_eid[2 * t + 1] = i1;
        g_wgt[2 * t] = e0 * inv; g_wgt[2 * t + 1] = e1 * inv;
        atomicAdd(&g_counts[i0], 1);
        atomicAdd(&g_counts[i1], 1);
    }
}

__global__ void scan_kernel()
{
    if (threadIdx.x != 0 || blockIdx.x != 0) return;
    int off = 0;
    for (int e = 0; e < NEXP; e++) {
        g_offs[e] = off; g_cursor[e] = off; off += g_counts[e];
    }
    g_offs[NEXP] = off;
    int t = 0;
    for (int e = 0; e < NEXP; e++) {
        int c = g_counts[e];
        for (int j = 0; j * 128 < c; j++) {
            g_te[t]  = e;
            g_tp0[t] = g_offs[e] + j * 128;
            int rem  = c - j * 128;
            g_tcnt[t] = rem < 128 ? rem : 128;
            t++;
        }
    }
    g_nmt[0] = t;
}

__global__ void scatter_kernel()
{
    int p = blockIdx.x * 256 + threadIdx.x;
    if (p >= NPAIR) return;
    int e = g_eid[p];
    int pos = atomicAdd(&g_cursor[e], 1);
    g_perm[pos] = p >> 1;
    g_p2p[p] = pos;
}

__global__ void combine_kernel(float* __restrict__ out)
{
    size_t i4 = (size_t)blockIdx.x * 256 + threadIdx.x;
    if (i4 >= (size_t)T_TOK * HID / 4) return;
    size_t i = i4 << 2;
    int t = (int)(i >> 12);
    int h = (int)(i & 4095);
    int p0 = g_p2p[2 * t], p1 = g_p2p[2 * t + 1];
    float w0 = g_wgt[2 * t], w1 = g_wgt[2 * t + 1];
    float4 y0 = *(const float4*)&g_y[(size_t)p0 * HID + h];
    float4 y1 = *(const float4*)&g_y[(size_t)p1 * HID + h];
    float4 o  = *(float4*)&out[i];
    o.x += w0 * y0.x + w1 * y1.x;
    o.y += w0 * y0.y + w1 * y1.y;
    o.z += w0 * y0.z + w1 * y1.z;
    o.w += w0 * y0.w + w1 * y1.w;
    *(float4*)&out[i] = o;
}

// ---------------------------------------------------------------------------
// Launch
// ---------------------------------------------------------------------------
extern "C" void kernel_launch(void* const* d_in, const int* in_sizes, int n_in,
                              void* d_out, int out_size)
{
    const float* x    = (const float*)d_in[0];
    const float* gw   = (const float*)d_in[1];
    const float* wgu  = (const float*)d_in[2];
    const float* wd   = (const float*)d_in[3];
    const float* swgu = (const float*)d_in[4];
    const float* swd  = (const float*)d_in[5];
    float* out = (float*)d_out;

    void *p_xs, *p_wsgu, *p_wsd, *p_wgu, *p_wd, *p_actsh, *p_actp, *p_y;
    cudaGetSymbolAddress(&p_xs,    g_xs);
    cudaGetSymbolAddress(&p_wsgu,  g_wsgu);
    cudaGetSymbolAddress(&p_wsd,   g_wsd);
    cudaGetSymbolAddress(&p_wgu,   g_wgu);
    cudaGetSymbolAddress(&p_wd,    g_wd);
    cudaGetSymbolAddress(&p_actsh, g_actsh);
    cudaGetSymbolAddress(&p_actp,  g_actp);
    cudaGetSymbolAddress(&p_y,     g_y);

    const int SMEM = NSTG * 32768;   // 98304, 2 CTAs/SM — R7-proven envelope
    cudaFuncSetAttribute(gemm_k<0,1>, cudaFuncAttributeMaxDynamicSharedMemorySize, SMEM);
    cudaFuncSetAttribute(gemm_k<0,0>, cudaFuncAttributeMaxDynamicSharedMemorySize, SMEM);
    cudaFuncSetAttribute(gemm_k<1,1>, cudaFuncAttributeMaxDynamicSharedMemorySize, SMEM);
    cudaFuncSetAttribute(gemm_k<2,0>, cudaFuncAttributeMaxDynamicSharedMemorySize, SMEM);

    auto blk4 = [](size_t n) { return (unsigned)((n / 4 + 255) / 256); };

    // fp32 -> fp16 converts
    cvt_kernel<<<blk4((size_t)T_TOK * HID),           256>>>((const float4*)x,    (uint2*)p_xs,   (size_t)T_TOK * HID / 4);
    cvt_kernel<<<blk4((size_t)2 * ISH * HID),         256>>>((const float4*)swgu, (uint2*)p_wsgu, (size_t)2 * ISH * HID / 4);
    cvt_kernel<<<blk4((size_t)HID * ISH),             256>>>((const float4*)swd,  (uint2*)p_wsd,  (size_t)HID * ISH / 4);
    cvt_kernel<<<blk4((size_t)NEXP * 2 * IMOE * HID), 256>>>((const float4*)wgu,  (uint2*)p_wgu,  (size_t)NEXP * 2 * IMOE * HID / 4);
    cvt_kernel<<<blk4((size_t)NEXP * HID * IMOE),     256>>>((const float4*)wd,   (uint2*)p_wd,   (size_t)NEXP * HID * IMOE / 4);

    // router + grouping metadata
    init_kernel<<<1, 32>>>();
    router_kernel<<<T_TOK, 128>>>(x, gw);
    scan_kernel<<<1, 32>>>();
    scatter_kernel<<<(NPAIR + 255) / 256, 256>>>();

    // shared MLP: gate_up (fused swiglu, 64 act cols per tile) then down -> out
    gemm_k<0,1><<<(T_TOK / 128) * (ISH / 64), 256, SMEM>>>(
        (const __half*)p_xs, (const __half*)p_wsgu, p_actsh,
        ISH, HID, 0, ISH / 64);
    gemm_k<0,0><<<(T_TOK / 128) * (HID / 128), 256, SMEM>>>(
        (const __half*)p_actsh, (const __half*)p_wsd, (void*)out,
        HID, ISH, 0, HID / 128);

    // grouped MoE: gate_up (gather + fused swiglu) then down -> g_y
    gemm_k<1,1><<<dim3(IMOE / 64, MAX_MT), 256, SMEM>>>(
        (const __half*)p_xs, (const __half*)p_wgu, p_actp,
        IMOE, HID, (size_t)(2 * IMOE) * HID, 0);
    gemm_k<2,0><<<dim3(HID / 128, MAX_MT), 256, SMEM>>>(
        (const __half*)p_actp, (const __half*)p_wd, p_y,
        HID, IMOE, (size_t)HID * IMOE, 0);

    // combine: out += w0*y[p0] + w1*y[p1]
    combine_kernel<<<blk4((size_t)T_TOK * HID), 256>>>(out);
}